// round 9
// baseline (speedup 1.0000x reference)
#include <cuda_runtime.h>
#include <cuda_bf16.h>

#define N_SRC   100000
#define N_DST   100000
#define N_EDGES 1250000
#define D_FEAT  64
#define HIDDEN  64
#define OUTD    128
#define CAP     48      // P(Poisson(12.5) > 48) ~ 1e-14 per bin

#define XS_STRIDE 132   // 128 + 4: conflict-free A-fragment loads
#define W2_STRIDE 136   // 128 + 8: conflict-free B-fragment loads

// Scratch (alloc-free rule: __device__ globals)
__device__ float              g_hs[N_SRC * HIDDEN];
__device__ int                g_cnt[N_DST];
__device__ unsigned long long g_bkt[(size_t)N_DST * CAP];   // (w_bits<<32 | src)
__device__ double             g_ssq;

// tf32 round (RNA) -> 32-bit pattern with low mantissa bits cleared
__device__ __forceinline__ unsigned int f2tf32(float x) {
    unsigned int r;
    asm("cvt.rna.tf32.f32 %0, %1;" : "=r"(r) : "f"(x));
    return r;
}

__device__ __forceinline__ void mma_tf32(float* c, const unsigned int* a,
                                         unsigned int b0, unsigned int b1) {
    asm volatile(
        "mma.sync.aligned.m16n8k8.row.col.f32.tf32.tf32.f32 "
        "{%0,%1,%2,%3}, {%4,%5,%6,%7}, {%8,%9}, {%0,%1,%2,%3};"
        : "+f"(c[0]), "+f"(c[1]), "+f"(c[2]), "+f"(c[3])
        : "r"(a[0]), "r"(a[1]), "r"(a[2]), "r"(a[3]), "r"(b0), "r"(b1));
}

// ---------------------------------------------------------------------------
// K1: zero counts + hs = relu(h_src @ W1 + b1)   (R4-proven)
// ---------------------------------------------------------------------------
__global__ void k_fc1(const float* __restrict__ h_src,
                      const float* __restrict__ W1,
                      const float* __restrict__ b1) {
    const int gt = blockIdx.x * blockDim.x + threadIdx.x;
    const int gs = gridDim.x * blockDim.x;
    for (int i = gt; i < N_DST; i += gs) g_cnt[i] = 0;
    if (gt == 0) g_ssq = 0.0;

    __shared__ float w1s[D_FEAT * HIDDEN];
    __shared__ float b1s[HIDDEN];
    __shared__ float xs[4 * D_FEAT];

    for (int i = threadIdx.x; i < D_FEAT * HIDDEN; i += blockDim.x) w1s[i] = W1[i];
    if (threadIdx.x < HIDDEN) b1s[threadIdx.x] = b1[threadIdx.x];

    const int r = threadIdx.x >> 6;
    const int o = threadIdx.x & 63;

    for (int base = blockIdx.x * 4; base < N_SRC; base += gridDim.x * 4) {
        __syncthreads();
        xs[threadIdx.x] = h_src[base * D_FEAT + threadIdx.x];
        __syncthreads();
        float acc = b1s[o];
        #pragma unroll
        for (int k = 0; k < D_FEAT; k++)
            acc = fmaf(xs[r * D_FEAT + k], w1s[k * HIDDEN + o], acc);
        g_hs[(base + r) * HIDDEN + o] = fmaxf(acc, 0.0f);
    }
}

// ---------------------------------------------------------------------------
// K2: bucket edges by destination (int atomics only)   (R4-proven)
// ---------------------------------------------------------------------------
__global__ void k_bucket(const float* __restrict__ ew,
                         const int*   __restrict__ src_idx,
                         const int*   __restrict__ dst_idx) {
    const int e = blockIdx.x * blockDim.x + threadIdx.x;
    if (e >= N_EDGES) return;
    const int   s = __ldg(src_idx + e);
    const int   d = __ldg(dst_idx + e);
    const float w = __ldg(ew + e);
    const int slot = atomicAdd(&g_cnt[d], 1);
    if (slot < CAP) {
        const unsigned long long p =
            ((unsigned long long)__float_as_uint(w) << 32) | (unsigned int)s;
        g_bkt[(size_t)d * CAP + slot] = p;
    }
}

// ---------------------------------------------------------------------------
// K3: fused gather-reduce + tf32-mma fc2 + sum-of-squares.
// Block handles 32 dsts/iter: warps gather 4 dsts each into shared X (tf32
// hi/lo planes), then each warp computes its 16-col slice of D = X @ W2 with
// mma.m16n8k8 tf32, 3-term split (xh*wh + xh*wl + xl*wh).
// ---------------------------------------------------------------------------
__global__ void k_gather_fc2(const float* __restrict__ h_dst,
                             const float* __restrict__ W2,
                             const float* __restrict__ b2,
                             float* __restrict__ out) {
    extern __shared__ float sm[];
    float*        w2s   = sm;                               // 128 x W2_STRIDE
    float*        b2s   = w2s + OUTD * W2_STRIDE;           // 128
    unsigned int* xs_hi = (unsigned int*)(b2s + OUTD);      // 32 x XS_STRIDE
    unsigned int* xs_lo = xs_hi + 32 * XS_STRIDE;           // 32 x XS_STRIDE

    for (int i = threadIdx.x; i < OUTD * OUTD; i += blockDim.x) {
        const int k = i >> 7, n = i & 127;
        w2s[k * W2_STRIDE + n] = W2[i];
    }
    if (threadIdx.x < OUTD) b2s[threadIdx.x] = b2[threadIdx.x];
    __syncthreads();

    const int warp = threadIdx.x >> 5;
    const int lane = threadIdx.x & 31;
    const int g    = lane >> 2;     // 0..7
    const int tig  = lane & 3;      // 0..3
    float lssq = 0.0f;

    for (int task = blockIdx.x; task < N_DST / 32; task += gridDim.x) {
        const int base = task * 32;

        // ==== gather phase: warp handles dsts base+4*warp .. +3 (R4 code) ====
        {
            const int wbase = base + warp * 4;
            int n[4];
            unsigned long long e0[4], e1[4];
            #pragma unroll
            for (int r = 0; r < 4; r++) {
                const int dst = wbase + r;
                int c = __ldg(&g_cnt[dst]);
                n[r] = (c > CAP) ? CAP : c;
                const unsigned long long* bkt = g_bkt + (size_t)dst * CAP;
                e0[r] = (lane      < n[r]) ? __ldg(bkt + lane)      : 0ull;
                e1[r] = (lane + 32 < n[r]) ? __ldg(bkt + lane + 32) : 0ull;
            }
            #pragma unroll
            for (int r = 0; r < 4; r++) {
                float ax = 0.0f, ay = 0.0f, wsum = 0.0f;
                const int n0 = (n[r] < 32) ? n[r] : 32;
                for (int i = 0; i < n0; i++) {
                    const unsigned long long p = __shfl_sync(0xFFFFFFFFu, e0[r], i);
                    const float w = __uint_as_float((unsigned int)(p >> 32));
                    const int   s = (int)(p & 0xffffffffu);
                    const float2 v = __ldg(((const float2*)(g_hs + (size_t)s * HIDDEN)) + lane);
                    ax = fmaf(v.x, w, ax);
                    ay = fmaf(v.y, w, ay);
                    wsum += w;
                }
                for (int i = 32; i < n[r]; i++) {
                    const unsigned long long p = __shfl_sync(0xFFFFFFFFu, e1[r], i - 32);
                    const float w = __uint_as_float((unsigned int)(p >> 32));
                    const int   s = (int)(p & 0xffffffffu);
                    const float2 v = __ldg(((const float2*)(g_hs + (size_t)s * HIDDEN)) + lane);
                    ax = fmaf(v.x, w, ax);
                    ay = fmaf(v.y, w, ay);
                    wsum += w;
                }
                const float inv = 1.0f / fmaxf(wsum, 1.0f);
                const float2 hd =
                    __ldg(((const float2*)(h_dst + (size_t)(wbase + r) * D_FEAT)) + lane);
                const int row = warp * 4 + r;
                float vals[4] = {ax * inv, ay * inv, hd.x, hd.y};
                int   cols[4] = {2 * lane, 2 * lane + 1, 64 + 2 * lane, 65 + 2 * lane};
                #pragma unroll
                for (int q = 0; q < 4; q++) {
                    const float x  = vals[q];
                    const unsigned int hb = f2tf32(x);
                    const float lo = x - __uint_as_float(hb);
                    xs_hi[row * XS_STRIDE + cols[q]] = hb;
                    xs_lo[row * XS_STRIDE + cols[q]] = f2tf32(lo);
                }
            }
        }
        __syncthreads();   // X planes ready

        // ==== mma phase: warp computes D[0:32][warp*16 : warp*16+16) ====
        {
            float c[2][2][4];
            #pragma unroll
            for (int m = 0; m < 2; m++)
                #pragma unroll
                for (int nt = 0; nt < 2; nt++) {
                    const int nb = warp * 16 + nt * 8;
                    c[m][nt][0] = b2s[nb + 2 * tig];
                    c[m][nt][1] = b2s[nb + 2 * tig + 1];
                    c[m][nt][2] = c[m][nt][0];
                    c[m][nt][3] = c[m][nt][1];
                }

            #pragma unroll 4
            for (int kt = 0; kt < 16; kt++) {
                const int k0 = kt * 8;
                unsigned int ah[2][4], al[2][4];
                #pragma unroll
                for (int m = 0; m < 2; m++) {
                    const int r0 = m * 16 + g, r1 = r0 + 8;
                    ah[m][0] = xs_hi[r0 * XS_STRIDE + k0 + tig];
                    ah[m][1] = xs_hi[r1 * XS_STRIDE + k0 + tig];
                    ah[m][2] = xs_hi[r0 * XS_STRIDE + k0 + tig + 4];
                    ah[m][3] = xs_hi[r1 * XS_STRIDE + k0 + tig + 4];
                    al[m][0] = xs_lo[r0 * XS_STRIDE + k0 + tig];
                    al[m][1] = xs_lo[r1 * XS_STRIDE + k0 + tig];
                    al[m][2] = xs_lo[r0 * XS_STRIDE + k0 + tig + 4];
                    al[m][3] = xs_lo[r1 * XS_STRIDE + k0 + tig + 4];
                }
                #pragma unroll
                for (int nt = 0; nt < 2; nt++) {
                    const int nb = warp * 16 + nt * 8;
                    const float w0 = w2s[(k0 + tig) * W2_STRIDE + nb + g];
                    const float w1 = w2s[(k0 + tig + 4) * W2_STRIDE + nb + g];
                    const unsigned int bh0 = f2tf32(w0);
                    const unsigned int bh1 = f2tf32(w1);
                    const unsigned int bl0 = f2tf32(w0 - __uint_as_float(bh0));
                    const unsigned int bl1 = f2tf32(w1 - __uint_as_float(bh1));
                    #pragma unroll
                    for (int m = 0; m < 2; m++) {
                        mma_tf32(c[m][nt], ah[m], bh0, bh1);
                        mma_tf32(c[m][nt], ah[m], bl0, bl1);
                        mma_tf32(c[m][nt], al[m], bh0, bh1);
                    }
                }
            }

            // relu + lssq + store (float2 per row-pair fragment)
            #pragma unroll
            for (int m = 0; m < 2; m++)
                #pragma unroll
                for (int nt = 0; nt < 2; nt++) {
                    const int nb = warp * 16 + nt * 8;
                    float v0 = fmaxf(c[m][nt][0], 0.0f);
                    float v1 = fmaxf(c[m][nt][1], 0.0f);
                    float v2 = fmaxf(c[m][nt][2], 0.0f);
                    float v3 = fmaxf(c[m][nt][3], 0.0f);
                    lssq += v0 * v0 + v1 * v1 + v2 * v2 + v3 * v3;
                    const int r0 = base + m * 16 + g;
                    float2* p0 = (float2*)(out + (size_t)r0 * OUTD + nb + 2 * tig);
                    float2* p1 = (float2*)(out + (size_t)(r0 + 8) * OUTD + nb + 2 * tig);
                    *p0 = make_float2(v0, v1);
                    *p1 = make_float2(v2, v3);
                }
        }
        __syncthreads();   // done reading X before next overwrite
    }

    // block reduction of sum-of-squares -> one double atomic per block
    #pragma unroll
    for (int off = 16; off > 0; off >>= 1)
        lssq += __shfl_down_sync(0xFFFFFFFFu, lssq, off);
    __shared__ float wssq[8];
    if (lane == 0) wssq[warp] = lssq;
    __syncthreads();
    if (threadIdx.x == 0) {
        float s = 0.0f;
        #pragma unroll
        for (int i = 0; i < 8; i++) s += wssq[i];
        atomicAdd(&g_ssq, (double)s);
    }
}

// ---------------------------------------------------------------------------
// K4: out *= 1/sqrt(g_ssq)
// ---------------------------------------------------------------------------
__global__ void k_scale(float* __restrict__ out) {
    const int i = blockIdx.x * blockDim.x + threadIdx.x;
    const int n4 = (N_DST * OUTD) / 4;
    if (i >= n4) return;
    const float inv = (float)(1.0 / sqrt(g_ssq));
    float4 v = ((float4*)out)[i];
    v.x *= inv; v.y *= inv; v.z *= inv; v.w *= inv;
    ((float4*)out)[i] = v;
}

// ---------------------------------------------------------------------------
extern "C" void kernel_launch(void* const* d_in, const int* in_sizes, int n_in,
                              void* d_out, int out_size) {
    const float* h_src = (const float*)d_in[0];
    const float* h_dst = (const float*)d_in[1];
    const float* ew    = (const float*)d_in[2];
    const float* W1    = (const float*)d_in[3];
    const float* b1    = (const float*)d_in[4];
    const float* W2    = (const float*)d_in[5];
    const float* b2    = (const float*)d_in[6];
    const int*   src   = (const int*)d_in[7];
    const int*   dst   = (const int*)d_in[8];
    float* out = (float*)d_out;

    k_fc1<<<2048, 256>>>(h_src, W1, b1);
    k_bucket<<<(N_EDGES + 255) / 256, 256>>>(ew, src, dst);

    {
        const int smem_bytes =
            (OUTD * W2_STRIDE + OUTD) * (int)sizeof(float) +
            2 * 32 * XS_STRIDE * (int)sizeof(unsigned int);
        cudaFuncSetAttribute(k_gather_fc2,
                             cudaFuncAttributeMaxDynamicSharedMemorySize,
                             smem_bytes);
        k_gather_fc2<<<296, 256, smem_bytes>>>(h_dst, W2, b2, out);
    }

    {
        const int n4 = (N_DST * OUTD) / 4;
        k_scale<<<(n4 + 255) / 256, 256>>>(out);
    }
}

// round 10
// speedup vs baseline: 1.0497x; 1.0497x over previous
#include <cuda_runtime.h>
#include <cuda_bf16.h>

#define N_SRC   100000
#define N_DST   100000
#define N_EDGES 1250000
#define D_FEAT  64
#define HIDDEN  64
#define OUTD    128
#define CAP     48      // P(Poisson(12.5) > 48) ~ 1e-14 per bin

#define SW 68           // smem word stride: (4g+tig) mod 32 distinct -> conflict-free

// Scratch (alloc-free rule: __device__ globals)
__device__ float              g_hs[N_SRC * HIDDEN];
__device__ int                g_cnt[N_DST];
__device__ unsigned long long g_bkt[(size_t)N_DST * CAP];   // (w_bits<<32 | src)
__device__ double             g_ssq;

__device__ __forceinline__ unsigned int packbf2(float a, float b) {
    __nv_bfloat162 t = __floats2bfloat162_rn(a, b);   // a -> low half
    return *(unsigned int*)&t;
}

__device__ __forceinline__ void mma_bf16(float* c, const unsigned int* a,
                                         unsigned int b0, unsigned int b1) {
    asm volatile(
        "mma.sync.aligned.m16n8k16.row.col.f32.bf16.bf16.f32 "
        "{%0,%1,%2,%3}, {%4,%5,%6,%7}, {%8,%9}, {%0,%1,%2,%3};"
        : "+f"(c[0]), "+f"(c[1]), "+f"(c[2]), "+f"(c[3])
        : "r"(a[0]), "r"(a[1]), "r"(a[2]), "r"(a[3]), "r"(b0), "r"(b1));
}

// ---------------------------------------------------------------------------
// K1: zero counts + hs = relu(h_src @ W1 + b1)   (R4-proven)
// ---------------------------------------------------------------------------
__global__ void k_fc1(const float* __restrict__ h_src,
                      const float* __restrict__ W1,
                      const float* __restrict__ b1) {
    const int gt = blockIdx.x * blockDim.x + threadIdx.x;
    const int gs = gridDim.x * blockDim.x;
    for (int i = gt; i < N_DST; i += gs) g_cnt[i] = 0;
    if (gt == 0) g_ssq = 0.0;

    __shared__ float w1s[D_FEAT * HIDDEN];
    __shared__ float b1s[HIDDEN];
    __shared__ float xs[4 * D_FEAT];

    for (int i = threadIdx.x; i < D_FEAT * HIDDEN; i += blockDim.x) w1s[i] = W1[i];
    if (threadIdx.x < HIDDEN) b1s[threadIdx.x] = b1[threadIdx.x];

    const int r = threadIdx.x >> 6;
    const int o = threadIdx.x & 63;

    for (int base = blockIdx.x * 4; base < N_SRC; base += gridDim.x * 4) {
        __syncthreads();
        xs[threadIdx.x] = h_src[base * D_FEAT + threadIdx.x];
        __syncthreads();
        float acc = b1s[o];
        #pragma unroll
        for (int k = 0; k < D_FEAT; k++)
            acc = fmaf(xs[r * D_FEAT + k], w1s[k * HIDDEN + o], acc);
        g_hs[(base + r) * HIDDEN + o] = fmaxf(acc, 0.0f);
    }
}

// ---------------------------------------------------------------------------
// K2: bucket edges by destination (int atomics only)   (R4-proven)
// ---------------------------------------------------------------------------
__global__ void k_bucket(const float* __restrict__ ew,
                         const int*   __restrict__ src_idx,
                         const int*   __restrict__ dst_idx) {
    const int e = blockIdx.x * blockDim.x + threadIdx.x;
    if (e >= N_EDGES) return;
    const int   s = __ldg(src_idx + e);
    const int   d = __ldg(dst_idx + e);
    const float w = __ldg(ew + e);
    const int slot = atomicAdd(&g_cnt[d], 1);
    if (slot < CAP) {
        const unsigned long long p =
            ((unsigned long long)__float_as_uint(w) << 32) | (unsigned int)s;
        g_bkt[(size_t)d * CAP + slot] = p;
    }
}

// ---------------------------------------------------------------------------
// K3: fused gather-reduce + bf16-mma fc2 (3-term split) + sum-of-squares.
// Block: 32 dsts/iter. W2^T pre-converted ONCE to bf16 hi/lo planes (bf16x2
// words). ~88KB smem -> 2 blocks/SM (16 warps, R4 occupancy restored).
// ---------------------------------------------------------------------------
__global__ void k_gather_fc2(const float* __restrict__ h_dst,
                             const float* __restrict__ W2,
                             const float* __restrict__ b2,
                             float* __restrict__ out) {
    extern __shared__ unsigned int smu[];
    unsigned int* wt_hi = smu;                     // [128 n][SW kw]
    unsigned int* wt_lo = wt_hi + OUTD * SW;
    unsigned int* x_hi  = wt_lo + OUTD * SW;       // [32 row][SW kw]
    unsigned int* x_lo  = x_hi + 32 * SW;
    float*        b2s   = (float*)(x_lo + 32 * SW);

    // W2^T -> bf16 hi/lo planes (once per block). wt[n][kw] packs k=2kw,2kw+1.
    for (int i = threadIdx.x; i < OUTD * 64; i += blockDim.x) {
        const int n = i >> 6, kw = i & 63;
        const float w0 = W2[(2 * kw) * OUTD + n];
        const float w1 = W2[(2 * kw + 1) * OUTD + n];
        const float h0 = __bfloat162float(__float2bfloat16(w0));
        const float h1 = __bfloat162float(__float2bfloat16(w1));
        wt_hi[n * SW + kw] = packbf2(h0, h1);
        wt_lo[n * SW + kw] = packbf2(w0 - h0, w1 - h1);
    }
    if (threadIdx.x < OUTD) b2s[threadIdx.x] = b2[threadIdx.x];
    __syncthreads();

    const int warp = threadIdx.x >> 5;
    const int lane = threadIdx.x & 31;
    const int g    = lane >> 2;     // 0..7
    const int tig  = lane & 3;      // 0..3
    float lssq = 0.0f;

    for (int task = blockIdx.x; task < N_DST / 32; task += gridDim.x) {
        const int base = task * 32;

        // ==== gather phase (R4-proven): warp handles 4 dsts ====
        {
            const int wbase = base + warp * 4;
            int n[4];
            unsigned long long e0[4], e1[4];
            #pragma unroll
            for (int r = 0; r < 4; r++) {
                const int dst = wbase + r;
                int c = __ldg(&g_cnt[dst]);
                n[r] = (c > CAP) ? CAP : c;
                const unsigned long long* bkt = g_bkt + (size_t)dst * CAP;
                e0[r] = (lane      < n[r]) ? __ldg(bkt + lane)      : 0ull;
                e1[r] = (lane + 32 < n[r]) ? __ldg(bkt + lane + 32) : 0ull;
            }
            #pragma unroll
            for (int r = 0; r < 4; r++) {
                float ax = 0.0f, ay = 0.0f, wsum = 0.0f;
                const int n0 = (n[r] < 32) ? n[r] : 32;
                for (int i = 0; i < n0; i++) {
                    const unsigned long long p = __shfl_sync(0xFFFFFFFFu, e0[r], i);
                    const float w = __uint_as_float((unsigned int)(p >> 32));
                    const int   s = (int)(p & 0xffffffffu);
                    const float2 v = __ldg(((const float2*)(g_hs + (size_t)s * HIDDEN)) + lane);
                    ax = fmaf(v.x, w, ax);
                    ay = fmaf(v.y, w, ay);
                    wsum += w;
                }
                for (int i = 32; i < n[r]; i++) {
                    const unsigned long long p = __shfl_sync(0xFFFFFFFFu, e1[r], i - 32);
                    const float w = __uint_as_float((unsigned int)(p >> 32));
                    const int   s = (int)(p & 0xffffffffu);
                    const float2 v = __ldg(((const float2*)(g_hs + (size_t)s * HIDDEN)) + lane);
                    ax = fmaf(v.x, w, ax);
                    ay = fmaf(v.y, w, ay);
                    wsum += w;
                }
                const float inv = 1.0f / fmaxf(wsum, 1.0f);
                const float2 hd =
                    __ldg(((const float2*)(h_dst + (size_t)(wbase + r) * D_FEAT)) + lane);
                const int row = warp * 4 + r;
                const float vx = ax * inv, vy = ay * inv;
                const float hx = __bfloat162float(__float2bfloat16(vx));
                const float hy = __bfloat162float(__float2bfloat16(vy));
                const float dx = __bfloat162float(__float2bfloat16(hd.x));
                const float dy = __bfloat162float(__float2bfloat16(hd.y));
                // cols 2lane,2lane+1 -> word lane; cols 64+2lane -> word 32+lane
                x_hi[row * SW + lane]      = packbf2(hx, hy);
                x_lo[row * SW + lane]      = packbf2(vx - hx, vy - hy);
                x_hi[row * SW + 32 + lane] = packbf2(dx, dy);
                x_lo[row * SW + 32 + lane] = packbf2(hd.x - dx, hd.y - dy);
            }
        }
        __syncthreads();   // X planes ready

        // ==== mma phase: warp computes D[0:32][warp*16 .. +16) ====
        {
            float c[2][2][4];
            #pragma unroll
            for (int m = 0; m < 2; m++)
                #pragma unroll
                for (int nt = 0; nt < 2; nt++) {
                    const int nb = warp * 16 + nt * 8;
                    c[m][nt][0] = b2s[nb + 2 * tig];
                    c[m][nt][1] = b2s[nb + 2 * tig + 1];
                    c[m][nt][2] = c[m][nt][0];
                    c[m][nt][3] = c[m][nt][1];
                }

            #pragma unroll
            for (int kt = 0; kt < 8; kt++) {
                const int kw0 = kt * 8;
                unsigned int ah[2][4], al[2][4];
                #pragma unroll
                for (int m = 0; m < 2; m++) {
                    const int r0 = m * 16 + g, r1 = r0 + 8;
                    ah[m][0] = x_hi[r0 * SW + kw0 + tig];
                    ah[m][1] = x_hi[r1 * SW + kw0 + tig];
                    ah[m][2] = x_hi[r0 * SW + kw0 + tig + 4];
                    ah[m][3] = x_hi[r1 * SW + kw0 + tig + 4];
                    al[m][0] = x_lo[r0 * SW + kw0 + tig];
                    al[m][1] = x_lo[r1 * SW + kw0 + tig];
                    al[m][2] = x_lo[r0 * SW + kw0 + tig + 4];
                    al[m][3] = x_lo[r1 * SW + kw0 + tig + 4];
                }
                #pragma unroll
                for (int nt = 0; nt < 2; nt++) {
                    const int nrow = warp * 16 + nt * 8 + g;
                    const unsigned int bh0 = wt_hi[nrow * SW + kw0 + tig];
                    const unsigned int bh1 = wt_hi[nrow * SW + kw0 + tig + 4];
                    const unsigned int bl0 = wt_lo[nrow * SW + kw0 + tig];
                    const unsigned int bl1 = wt_lo[nrow * SW + kw0 + tig + 4];
                    #pragma unroll
                    for (int m = 0; m < 2; m++) {
                        mma_bf16(c[m][nt], ah[m], bh0, bh1);
                        mma_bf16(c[m][nt], al[m], bh0, bh1);
                        mma_bf16(c[m][nt], ah[m], bl0, bl1);
                    }
                }
            }

            // relu + lssq + store
            #pragma unroll
            for (int m = 0; m < 2; m++)
                #pragma unroll
                for (int nt = 0; nt < 2; nt++) {
                    const int nb = warp * 16 + nt * 8;
                    float v0 = fmaxf(c[m][nt][0], 0.0f);
                    float v1 = fmaxf(c[m][nt][1], 0.0f);
                    float v2 = fmaxf(c[m][nt][2], 0.0f);
                    float v3 = fmaxf(c[m][nt][3], 0.0f);
                    lssq += v0 * v0 + v1 * v1 + v2 * v2 + v3 * v3;
                    const int r0 = base + m * 16 + g;
                    float2* p0 = (float2*)(out + (size_t)r0 * OUTD + nb + 2 * tig);
                    float2* p1 = (float2*)(out + (size_t)(r0 + 8) * OUTD + nb + 2 * tig);
                    *p0 = make_float2(v0, v1);
                    *p1 = make_float2(v2, v3);
                }
        }
        __syncthreads();   // done reading X before next overwrite
    }

    // block reduction of sum-of-squares -> one double atomic per block
    #pragma unroll
    for (int off = 16; off > 0; off >>= 1)
        lssq += __shfl_down_sync(0xFFFFFFFFu, lssq, off);
    __shared__ float wssq[8];
    if (lane == 0) wssq[warp] = lssq;
    __syncthreads();
    if (threadIdx.x == 0) {
        float s = 0.0f;
        #pragma unroll
        for (int i = 0; i < 8; i++) s += wssq[i];
        atomicAdd(&g_ssq, (double)s);
    }
}

// ---------------------------------------------------------------------------
// K4: out *= 1/sqrt(g_ssq)
// ---------------------------------------------------------------------------
__global__ void k_scale(float* __restrict__ out) {
    const int i = blockIdx.x * blockDim.x + threadIdx.x;
    const int n4 = (N_DST * OUTD) / 4;
    if (i >= n4) return;
    const float inv = (float)(1.0 / sqrt(g_ssq));
    float4 v = ((float4*)out)[i];
    v.x *= inv; v.y *= inv; v.z *= inv; v.w *= inv;
    ((float4*)out)[i] = v;
}

// ---------------------------------------------------------------------------
extern "C" void kernel_launch(void* const* d_in, const int* in_sizes, int n_in,
                              void* d_out, int out_size) {
    const float* h_src = (const float*)d_in[0];
    const float* h_dst = (const float*)d_in[1];
    const float* ew    = (const float*)d_in[2];
    const float* W1    = (const float*)d_in[3];
    const float* b1    = (const float*)d_in[4];
    const float* W2    = (const float*)d_in[5];
    const float* b2    = (const float*)d_in[6];
    const int*   src   = (const int*)d_in[7];
    const int*   dst   = (const int*)d_in[8];
    float* out = (float*)d_out;

    k_fc1<<<2048, 256>>>(h_src, W1, b1);
    k_bucket<<<(N_EDGES + 255) / 256, 256>>>(ew, src, dst);

    {
        const int smem_bytes =
            (2 * OUTD * SW + 2 * 32 * SW) * (int)sizeof(unsigned int) +
            OUTD * (int)sizeof(float);
        cudaFuncSetAttribute(k_gather_fc2,
                             cudaFuncAttributeMaxDynamicSharedMemorySize,
                             smem_bytes);
        k_gather_fc2<<<296, 256, smem_bytes>>>(h_dst, W2, b2, out);
    }

    {
        const int n4 = (N_DST * OUTD) / 4;
        k_scale<<<(n4 + 255) / 256, 256>>>(out);
    }
}